// round 2
// baseline (speedup 1.0000x reference)
#include <cuda_runtime.h>
#include <math.h>

#define BB 64
#define SS 2048
#define II 512
#define HH 512

#define NGB 16   // batch groups
#define NGJ 8    // j slices per group
#define BC  4    // batches per group
#define JC  64   // j per slice

// per-group arrival counters (reset by reset_kernel each launch)
__device__ int g_sync[NGB];

__global__ void reset_kernel() {
    if (threadIdx.x < NGB) g_sync[threadIdx.x] = 0;
}

// ---------------------------------------------------------------------------
// Kernel 1: xproj GEMM.  P[m][j] = sum_i X[m][i] * Wx[j][i]
// X is (B*S, I) row-major, Wx is (H, I) row-major.  64x64 tile, k-chunk 16,
// 256 threads, 4x4 register micro-tile.  Writes pre-activations into out.
// ---------------------------------------------------------------------------
__global__ __launch_bounds__(256) void xproj_kernel(
    const float* __restrict__ X,
    const float* __restrict__ Wx,
    float* __restrict__ P)
{
    __shared__ float Xs[16][64];
    __shared__ float Ws[16][64];

    const int tid  = threadIdx.x;
    const int m0   = blockIdx.x * 64;
    const int j0   = blockIdx.y * 64;
    const int tx   = tid & 15;        // m micro-tile index
    const int ty   = tid >> 4;        // j micro-tile index
    const int lrow = tid >> 2;        // 0..63: row within tile to load
    const int lk4  = (tid & 3) * 4;   // 0,4,8,12: k offset to load

    const float* xg = X  + (size_t)(m0 + lrow) * II + lk4;
    const float* wg = Wx + (size_t)(j0 + lrow) * II + lk4;

    float acc[4][4];
#pragma unroll
    for (int r = 0; r < 4; ++r)
#pragma unroll
        for (int c = 0; c < 4; ++c) acc[r][c] = 0.0f;

    for (int kc = 0; kc < II; kc += 16) {
        float4 xa = *(const float4*)(xg + kc);
        float4 wa = *(const float4*)(wg + kc);
        __syncthreads();
        Xs[lk4 + 0][lrow] = xa.x; Xs[lk4 + 1][lrow] = xa.y;
        Xs[lk4 + 2][lrow] = xa.z; Xs[lk4 + 3][lrow] = xa.w;
        Ws[lk4 + 0][lrow] = wa.x; Ws[lk4 + 1][lrow] = wa.y;
        Ws[lk4 + 2][lrow] = wa.z; Ws[lk4 + 3][lrow] = wa.w;
        __syncthreads();
#pragma unroll
        for (int k = 0; k < 16; ++k) {
            float4 a  = *(const float4*)&Xs[k][tx * 4];
            float4 bq = *(const float4*)&Ws[k][ty * 4];
            acc[0][0] += a.x * bq.x; acc[0][1] += a.x * bq.y;
            acc[0][2] += a.x * bq.z; acc[0][3] += a.x * bq.w;
            acc[1][0] += a.y * bq.x; acc[1][1] += a.y * bq.y;
            acc[1][2] += a.y * bq.z; acc[1][3] += a.y * bq.w;
            acc[2][0] += a.z * bq.x; acc[2][1] += a.z * bq.y;
            acc[2][2] += a.z * bq.z; acc[2][3] += a.z * bq.w;
            acc[3][0] += a.w * bq.x; acc[3][1] += a.w * bq.y;
            acc[3][2] += a.w * bq.z; acc[3][3] += a.w * bq.w;
        }
    }

#pragma unroll
    for (int r = 0; r < 4; ++r) {
        float4 o = make_float4(acc[r][0], acc[r][1], acc[r][2], acc[r][3]);
        *(float4*)(P + (size_t)(m0 + tx * 4 + r) * HH + j0 + ty * 4) = o;
    }
}

// ---------------------------------------------------------------------------
// Kernel 2: persistent recurrent scan.
// Grid = 128 CTAs: cta = bg*8 + jg.  CTA (bg,jg) owns batches [bg*4, bg*4+4)
// and output columns [jg*64, jg*64+64).  Wh slice (64x512) lives transposed
// in SMEM for the whole kernel.  h state is exchanged through `out` (the
// outputs ARE the hidden states) with a per-group release/acquire counter.
// ---------------------------------------------------------------------------
#define SCAN_SMEM (512*64*4 + 4*512*4 + 8*4*64*4)   // Whs + hs + red = 147456 B

__global__ __launch_bounds__(256, 1) void scan_kernel(
    const float* __restrict__ h0,
    const float* __restrict__ Wh,
    const float* __restrict__ bh,
    float* __restrict__ out,        // (B,S,H): holds P on entry, h_t on exit
    float* __restrict__ hlast)      // (B,H)
{
    extern __shared__ float sm[];
    float* Whs = sm;                 // [512][64]  Wh transposed: Whs[k][jl]
    float* hs  = sm + 512 * 64;      // [4][512]   current h rows
    float* red = hs + 4 * 512;       // [8][4][64] k-split partials

    const int tid = threadIdx.x;
    const int bg  = blockIdx.x >> 3;     // 0..15
    const int jg  = blockIdx.x & 7;      // 0..7
    const int b0  = bg * BC;
    const int j0  = jg * JC;

    // ---- load Wh slice transposed into SMEM (once) ----
    {
        const int jl = tid >> 2;             // 0..63
        const int kb = (tid & 3) * 128;      // k chunk base
        const float* src = Wh + (size_t)(j0 + jl) * HH + kb;
        for (int kk = 0; kk < 128; kk += 4) {
            float4 v = *(const float4*)(src + kk);
            Whs[(kb + kk + 0) * 64 + jl] = v.x;
            Whs[(kb + kk + 1) * 64 + jl] = v.y;
            Whs[(kb + kk + 2) * 64 + jl] = v.z;
            Whs[(kb + kk + 3) * 64 + jl] = v.w;
        }
    }

    // compute mapping: warp = k-chunk, lane covers 2 j's, all 4 b's
    const int w     = tid >> 5;          // 0..7  -> k in [w*64, w*64+64)
    const int lane  = tid & 31;
    const int jl2   = lane * 2;
    const int kbase = w * 64;

    // reduce / output mapping: one thread per output element
    const int rb = tid >> 6;             // 0..3
    const int rj = tid & 63;             // 0..63
    const float bias = bh[j0 + rj];

    // h-load mapping: 4 rows x 512, 8 floats per thread
    const int hrow = tid >> 6;           // 0..3
    const int hk   = (tid & 63) * 8;     // 0..504

    __syncthreads();

    for (int t = 0; t < SS; ++t) {
        // ---- load h_{t-1} rows into SMEM (bypass L1 for cross-CTA data) ----
        const float* hp = (t == 0)
            ? (h0 + (size_t)(b0 + hrow) * HH + hk)
            : (out + ((size_t)(b0 + hrow) * SS + (t - 1)) * HH + hk);
        float4 hv0 = __ldcg((const float4*)hp);
        float4 hv1 = __ldcg((const float4*)(hp + 4));

        // prefetch this thread's pre-activation P[b,t,j] (independent of h)
        const size_t oidx = ((size_t)(b0 + rb) * SS + t) * HH + j0 + rj;
        const float pv = __ldcg(out + oidx);

        *(float4*)&hs[hrow * 512 + hk]     = hv0;
        *(float4*)&hs[hrow * 512 + hk + 4] = hv1;
        __syncthreads();

        // ---- partial GEMM: acc[b][0..1] over this warp's k-chunk ----
        float acc[4][2] = {{0,0},{0,0},{0,0},{0,0}};
#pragma unroll
        for (int kk = 0; kk < 64; kk += 4) {
            float ha[4][4];
#pragma unroll
            for (int b = 0; b < 4; ++b)
                *(float4*)ha[b] = *(const float4*)&hs[b * 512 + kbase + kk];
#pragma unroll
            for (int u = 0; u < 4; ++u) {
                const float2 wv = *(const float2*)&Whs[(kbase + kk + u) * 64 + jl2];
#pragma unroll
                for (int b = 0; b < 4; ++b) {
                    acc[b][0] += ha[b][u] * wv.x;
                    acc[b][1] += ha[b][u] * wv.y;
                }
            }
        }

#pragma unroll
        for (int b = 0; b < 4; ++b)
            *(float2*)&red[(w * 4 + b) * 64 + jl2] = make_float2(acc[b][0], acc[b][1]);
        __syncthreads();

        // ---- reduce k-split partials, add P + bias, tanh, write h_t ----
        float sum = pv + bias;
#pragma unroll
        for (int ww = 0; ww < 8; ++ww)
            sum += red[(ww * 4 + rb) * 64 + rj];
        const float hnew = tanhf(sum);
        __stcg(out + oidx, hnew);
        if (t == SS - 1)
            hlast[(size_t)(b0 + rb) * HH + j0 + rj] = hnew;

        // ---- group barrier: release own slice, acquire peers' slices ----
        if (t < SS - 1) {
            __threadfence();
            __syncthreads();
            if (tid == 0) {
                atomicAdd(&g_sync[bg], 1);
                const int target = NGJ * (t + 1);
                while (atomicAdd(&g_sync[bg], 0) < target) { __nanosleep(64); }
                __threadfence();
            }
            __syncthreads();
        }
    }
}

// ---------------------------------------------------------------------------
extern "C" void kernel_launch(void* const* d_in, const int* in_sizes, int n_in,
                              void* d_out, int out_size) {
    const float* x   = (const float*)d_in[0];   // (B,S,I)
    const float* h0  = (const float*)d_in[1];   // (B,H)
    const float* Wx  = (const float*)d_in[2];   // (H,I)
    const float* Wh  = (const float*)d_in[3];   // (H,H)
    const float* bh  = (const float*)d_in[4];   // (H,)
    float* out   = (float*)d_out;                          // (B,S,H)
    float* hlast = out + (size_t)BB * SS * HH;             // (B,H)

    cudaFuncSetAttribute(scan_kernel,
                         cudaFuncAttributeMaxDynamicSharedMemorySize, SCAN_SMEM);

    reset_kernel<<<1, 32>>>();

    dim3 gg((BB * SS) / 64, HH / 64);   // (2048, 8)
    xproj_kernel<<<gg, 256>>>(x, Wx, out);

    scan_kernel<<<128, 256, SCAN_SMEM>>>(h0, Wh, bh, out, hlast);
}